// round 15
// baseline (speedup 1.0000x reference)
#include <cuda_runtime.h>
#include <cuda_bf16.h>
#include <stdint.h>

#define NODES_CAP 100000     // scratch capacity (matches dataset N)
#define DIM       32

// Scratch for XW = X @ W (12.8 MB). Static __device__ global — no allocation.
__device__ float g_XW[NODES_CAP * DIM];

// ---------------------------------------------------------------------------
// Kernel 1: XW[r][j] = sum_k X[r][k] * W[k][j]
// Block = 256 threads = 8 warps, 16 rows per warp (128 rows/block).
// No shuffles: each lane holds W[:,lane] in 32 registers; x values come from
// a shared-memory X tile via uniform LDS.128 (4 k-values per load).
// ---------------------------------------------------------------------------
#define XW_ROWS_PER_BLOCK 128
#define XW_ROWS_PER_WARP  16

__global__ void __launch_bounds__(256)
xw_kernel(const float* __restrict__ X, const float* __restrict__ W, int n)
{
    __shared__ float Ws[DIM * DIM];                    // 4 KB
    __shared__ float Xs[XW_ROWS_PER_BLOCK * DIM];      // 16 KB

    int tid  = threadIdx.x;
    int warp = tid >> 5;
    int lane = tid & 31;
    int row0 = blockIdx.x * XW_ROWS_PER_BLOCK;
    int rows = n - row0;
    if (rows > XW_ROWS_PER_BLOCK) rows = XW_ROWS_PER_BLOCK;

    // Stage W (coalesced) and the X tile (coalesced float4).
    #pragma unroll
    for (int i = tid; i < DIM * DIM; i += 256)
        Ws[i] = W[i];
    {
        const float4* __restrict__ X4 = (const float4*)(X + (size_t)row0 * DIM);
        float4* Xs4 = (float4*)Xs;
        int n4 = rows * (DIM / 4);
        for (int i = tid; i < n4; i += 256)
            Xs4[i] = __ldcs(&X4[i]);
    }
    __syncthreads();

    // Each lane caches its W column in registers.
    float wc[DIM];
    #pragma unroll
    for (int k = 0; k < DIM; k++)
        wc[k] = Ws[k * DIM + lane];

    #pragma unroll 4
    for (int r = 0; r < XW_ROWS_PER_WARP; r++) {
        int lrow = warp * XW_ROWS_PER_WARP + r;
        if (lrow >= rows) break;
        const float4* xs = (const float4*)(Xs + lrow * DIM);  // uniform addr
        float acc = 0.0f;
        #pragma unroll
        for (int kk = 0; kk < DIM / 4; kk++) {
            float4 x4 = xs[kk];
            acc = fmaf(x4.x, wc[4 * kk + 0], acc);
            acc = fmaf(x4.y, wc[4 * kk + 1], acc);
            acc = fmaf(x4.z, wc[4 * kk + 2], acc);
            acc = fmaf(x4.w, wc[4 * kk + 3], acc);
        }
        g_XW[(size_t)(row0 + lrow) * DIM + lane] = acc;
    }
}

// ---------------------------------------------------------------------------
// Kernel 2: out[r][:] = sum over e in [rp[r], rp[r+1]) of XW[ci[e]][:]
// One warp per row. eo = lane>>3 selects 1 of 4 edges per gather group,
// fo = lane&7 selects a float4 chunk. Per 32-edge chunk: ONE coalesced ci
// load (ci[base+lane]) resolves all indices; per-lane-source shuffles
// (srcLane = 4g+eo) distribute them to the 8 gather groups, whose 8 warp
// LDG.128s (4 edges x 128B each) then issue back-to-back — MLP ~8 per chunk
// instead of 2-4 with per-iteration dependent ci loads.
// ---------------------------------------------------------------------------
__global__ void __launch_bounds__(256)
gather_kernel(const int* __restrict__ rp, const int* __restrict__ ci,
              float* __restrict__ out, int n)
{
    int warp = (blockIdx.x * 256 + threadIdx.x) >> 5;
    int lane = threadIdx.x & 31;
    if (warp >= n) return;

    int beg = __ldg(&rp[warp]);
    int end = __ldg(&rp[warp + 1]);

    int eo = lane >> 3;        // which of 4 edges in a gather group
    int fo = lane & 7;         // which float4 chunk of the 32-float row

    const float4* __restrict__ xw4 = (const float4*)g_XW;

    float4 a0 = make_float4(0.f, 0.f, 0.f, 0.f);
    float4 a1 = make_float4(0.f, 0.f, 0.f, 0.f);

    for (int base = beg; base < end; base += 32) {
        int m = end - base;
        if (m > 32) m = 32;

        // One coalesced index load covers the whole 32-edge chunk.
        int c = (lane < m) ? __ldcs(&ci[base + lane]) : 0;

        // 8 gather groups; all LDGs independent once c arrives.
        #pragma unroll
        for (int g = 0; g < 8; g += 2) {
            int eA = 4 * g + eo;          // edge offset within chunk
            int eB = 4 * (g + 1) + eo;
            int iA = __shfl_sync(0xffffffffu, c, eA);
            int iB = __shfl_sync(0xffffffffu, c, eB);
            if (eA < m) {
                float4 t = xw4[iA * 8 + fo];
                a0.x += t.x; a0.y += t.y; a0.z += t.z; a0.w += t.w;
            }
            if (eB < m) {
                float4 t = xw4[iB * 8 + fo];
                a1.x += t.x; a1.y += t.y; a1.z += t.z; a1.w += t.w;
            }
        }
    }

    float4 acc;
    acc.x = a0.x + a1.x;
    acc.y = a0.y + a1.y;
    acc.z = a0.z + a1.z;
    acc.w = a0.w + a1.w;

    // Reduce across the 4 eo groups (lanes differing in bits 3 and 4).
    #pragma unroll
    for (int mm = 8; mm <= 16; mm <<= 1) {
        acc.x += __shfl_xor_sync(0xffffffffu, acc.x, mm);
        acc.y += __shfl_xor_sync(0xffffffffu, acc.y, mm);
        acc.z += __shfl_xor_sync(0xffffffffu, acc.z, mm);
        acc.w += __shfl_xor_sync(0xffffffffu, acc.w, mm);
    }

    // Lanes 0-7 hold the full row sum for their chunk: one 128B store.
    if (lane < 8) {
        float4* out4 = (float4*)(out + (size_t)warp * DIM);
        __stcs(&out4[fo], acc);    // 0 for empty rows (d_out poisoned)
    }
}

// ---------------------------------------------------------------------------
// Launch
// Inputs (metadata order): 0=X [N*32 f32], 1=weights [32*32 f32],
// 2=row_pointers [N+1 i32], 3=column_index [E i32], 4..=dummies.
// Output: [N*32] f32.
// ---------------------------------------------------------------------------
extern "C" void kernel_launch(void* const* d_in, const int* in_sizes, int n_in,
                              void* d_out, int out_size)
{
    const float* X  = (const float*)d_in[0];
    const float* W  = (const float*)d_in[1];
    const int*   rp = (const int*)d_in[2];
    const int*   ci = (const int*)d_in[3];
    float*       out = (float*)d_out;

    int n = in_sizes[2] - 1;          // rows from row_pointers length
    if (n > NODES_CAP) n = NODES_CAP; // scratch capacity guard

    int xw_blocks = (n + XW_ROWS_PER_BLOCK - 1) / XW_ROWS_PER_BLOCK;
    xw_kernel<<<xw_blocks, 256>>>(X, W, n);

    const int warps_per_block = 256 / 32;
    int g_blocks = (n + warps_per_block - 1) / warps_per_block;
    gather_kernel<<<g_blocks, 256>>>(rp, ci, out, n);
}